// round 1
// baseline (speedup 1.0000x reference)
#include <cuda_runtime.h>

// Problem constants
#define BQ  4
#define CC  256
#define CQK 32
#define NN  4096

// Scratch (no cudaMalloc allowed): q [B,N,32], k [B,32,N], v [B,256,N]
__device__ float g_q[BQ * NN * CQK];
__device__ float g_k[BQ * CQK * NN];
__device__ float g_v[BQ * CC * NN];

// ======================== projection kernel ========================
// q = Wq@x + bq ; k = Wk@x + bk ; v = Wv@x + bv  (1x1 convs == per-token linear)
#define PTOK      128
#define PTHREADS  256
#define XS_STRIDE 132   // 128 + 4 pad
#define WS_STRIDE 264   // 256 + 8 pad

__global__ __launch_bounds__(PTHREADS)
void proj_kernel(const float* __restrict__ x,
                 const float* __restrict__ Wq, const float* __restrict__ bq,
                 const float* __restrict__ Wk, const float* __restrict__ bk,
                 const float* __restrict__ Wv, const float* __restrict__ bv)
{
    extern __shared__ float sm[];
    float* xs = sm;                         // [256][132]
    float* ws = sm + CC * XS_STRIDE;        // [8][264]

    const int b    = blockIdx.y;
    const int n0   = blockIdx.x * PTOK;
    const int tid  = threadIdx.x;
    const int warp = tid >> 5;
    const int lane = tid & 31;

    // Stage x tile [256 channels][128 tokens] into SMEM (coalesced float4 along n)
    const float* xb = x + (size_t)b * CC * NN;
    #pragma unroll
    for (int it = 0; it < (CC * PTOK / 4) / PTHREADS; ++it) {
        int idx = tid + it * PTHREADS;      // 0..8191 float4 slots
        int c   = idx >> 5;                 // PTOK/4 == 32
        int j4  = idx & 31;
        float4 v = *(const float4*)(xb + (size_t)c * NN + n0 + 4 * j4);
        *(float4*)(xs + c * XS_STRIDE + 4 * j4) = v;
    }
    __syncthreads();

    // 320 output channels round-robin across 8 warps; each lane owns 4 tokens
    for (int oi = warp; oi < 320; oi += 8) {
        const float* wrow;
        float bias;
        if (oi < 32)      { wrow = Wq + oi * CC;        bias = bq[oi]; }
        else if (oi < 64) { wrow = Wk + (oi - 32) * CC; bias = bk[oi - 32]; }
        else              { wrow = Wv + (oi - 64) * CC; bias = bv[oi - 64]; }

        float* wbuf = ws + warp * WS_STRIDE;
        #pragma unroll
        for (int k8 = 0; k8 < 8; ++k8) wbuf[lane + 32 * k8] = wrow[lane + 32 * k8];
        __syncwarp();

        float a0 = 0.f, a1 = 0.f, a2 = 0.f, a3 = 0.f;
        const float* xp = xs + 4 * lane;
        #pragma unroll 8
        for (int c = 0; c < CC; ++c) {
            float  wv = wbuf[c];
            float4 xv = *(const float4*)(xp + c * XS_STRIDE);
            a0 += wv * xv.x; a1 += wv * xv.y; a2 += wv * xv.z; a3 += wv * xv.w;
        }
        a0 += bias; a1 += bias; a2 += bias; a3 += bias;

        const int t0 = n0 + 4 * lane;
        if (oi < 32) {
            float* qp = g_q + ((size_t)b * NN + t0) * CQK + oi;
            qp[0] = a0; qp[CQK] = a1; qp[2 * CQK] = a2; qp[3 * CQK] = a3;
        } else if (oi < 64) {
            *(float4*)(g_k + ((size_t)b * CQK + (oi - 32)) * NN + t0) =
                make_float4(a0, a1, a2, a3);
        } else {
            *(float4*)(g_v + ((size_t)b * CC + (oi - 64)) * NN + t0) =
                make_float4(a0, a1, a2, a3);
        }
        __syncwarp();   // all lanes done with wbuf before restage
    }
}

// ======================== flash attention kernel ========================
// Per CTA: 64 query rows; loop over 64-key tiles; online softmax; O[64][256] fp32 in regs.
#define BM 64
#define BN 64
#define FTHREADS  512
#define QS_STRIDE 36
#define KS_STRIDE 68
#define SS_STRIDE 68
#define VS_STRIDE 262   // even (float2-aligned), conflict-free PV reads

__global__ __launch_bounds__(FTHREADS)
void attn_kernel(const float* __restrict__ x, float* __restrict__ out)
{
    extern __shared__ float sm[];
    float* qs   = sm;                        // [64][36]
    float* ks   = qs  + BM * QS_STRIDE;      // [32][68]
    float* Ssm  = ks  + CQK * KS_STRIDE;     // [64][68]
    float* vs   = Ssm + BM * SS_STRIDE;      // [64][262]
    float* m_s  = vs  + BN * VS_STRIDE;      // [64]
    float* l_s  = m_s + BM;                  // [64]
    float* sc_s = l_s + BM;                  // [64]

    const int b   = blockIdx.y;
    const int m0  = blockIdx.x * BM;
    const int tid = threadIdx.x;

    // load Q block [64][32]
    {
        int m = tid >> 3, k4 = tid & 7;
        *(float4*)(qs + m * QS_STRIDE + 4 * k4) =
            *(const float4*)(g_q + ((size_t)b * NN + m0 + m) * CQK + 4 * k4);
    }
    if (tid < BM) { m_s[tid] = -1e30f; l_s[tid] = 0.f; }

    const int ry = tid >> 4;   // 0..31 -> rows {ry, ry+32}
    const int cx = tid & 15;   // 0..15 -> S cols {4cx..4cx+3} / O cols {2cx+32i}

    float o0[16], o1[16];
    #pragma unroll
    for (int i = 0; i < 16; ++i) { o0[i] = 0.f; o1[i] = 0.f; }

    const float* kb = g_k + (size_t)b * CQK * NN;
    const float* vb = g_v + (size_t)b * CC * NN;

    for (int nt = 0; nt < NN; nt += BN) {
        __syncthreads();   // also covers initial qs/m_s init; protects tile reuse

        // load K tile [32][64]
        {
            int kk = tid >> 4, j4 = tid & 15;
            *(float4*)(ks + kk * KS_STRIDE + 4 * j4) =
                *(const float4*)(kb + (size_t)kk * NN + nt + 4 * j4);
        }
        // load V tile transposed into vs[token][channel]
        #pragma unroll
        for (int it = 0; it < 8; ++it) {
            int idx = tid + it * FTHREADS;   // 0..4095 float4 slots
            int c = idx >> 4, j4 = idx & 15;
            float4 v = *(const float4*)(vb + (size_t)c * NN + nt + 4 * j4);
            vs[(4 * j4 + 0) * VS_STRIDE + c] = v.x;
            vs[(4 * j4 + 1) * VS_STRIDE + c] = v.y;
            vs[(4 * j4 + 2) * VS_STRIDE + c] = v.z;
            vs[(4 * j4 + 3) * VS_STRIDE + c] = v.w;
        }
        __syncthreads();

        // S[64][64] = Q · K   (each thread: 2 rows x 4 cols)
        {
            float a0=0,a1=0,a2=0,a3=0, b0=0,b1=0,b2=0,b3=0;
            const float* q0 = qs + ry * QS_STRIDE;
            const float* q1 = qs + (ry + 32) * QS_STRIDE;
            #pragma unroll
            for (int kk = 0; kk < CQK; ++kk) {
                float4 kv = *(const float4*)(ks + kk * KS_STRIDE + 4 * cx);
                float qa = q0[kk], qb = q1[kk];
                a0 += qa * kv.x; a1 += qa * kv.y; a2 += qa * kv.z; a3 += qa * kv.w;
                b0 += qb * kv.x; b1 += qb * kv.y; b2 += qb * kv.z; b3 += qb * kv.w;
            }
            *(float4*)(Ssm + ry * SS_STRIDE + 4 * cx)        = make_float4(a0,a1,a2,a3);
            *(float4*)(Ssm + (ry + 32) * SS_STRIDE + 4 * cx) = make_float4(b0,b1,b2,b3);
        }
        __syncthreads();

        // online softmax: 8 threads per row
        {
            int row = tid >> 3, g = tid & 7;
            float* srow = Ssm + row * SS_STRIDE;
            float mx = -1e30f;
            #pragma unroll
            for (int j = 0; j < 8; ++j) mx = fmaxf(mx, srow[g + 8 * j]);
            mx = fmaxf(mx, __shfl_xor_sync(0xffffffffu, mx, 4));
            mx = fmaxf(mx, __shfl_xor_sync(0xffffffffu, mx, 2));
            mx = fmaxf(mx, __shfl_xor_sync(0xffffffffu, mx, 1));
            float m_old = m_s[row];
            float m_new = fmaxf(m_old, mx);
            float ts = 0.f;
            #pragma unroll
            for (int j = 0; j < 8; ++j) {
                float p = __expf(srow[g + 8 * j] - m_new);
                srow[g + 8 * j] = p;
                ts += p;
            }
            ts += __shfl_xor_sync(0xffffffffu, ts, 4);
            ts += __shfl_xor_sync(0xffffffffu, ts, 2);
            ts += __shfl_xor_sync(0xffffffffu, ts, 1);
            if (g == 0) {
                float sc = __expf(m_old - m_new);
                sc_s[row] = sc;
                l_s[row]  = l_s[row] * sc + ts;
                m_s[row]  = m_new;
            }
        }
        __syncthreads();

        // O = O*scale + P · V'   (hot loop: FFMA-bound)
        {
            float s0 = sc_s[ry], s1 = sc_s[ry + 32];
            #pragma unroll
            for (int i = 0; i < 16; ++i) { o0[i] *= s0; o1[i] *= s1; }
            const float* p0r = Ssm + ry * SS_STRIDE;
            const float* p1r = Ssm + (ry + 32) * SS_STRIDE;
            #pragma unroll 4
            for (int n = 0; n < BN; ++n) {
                float p0 = p0r[n], p1 = p1r[n];
                const float* vrow = vs + n * VS_STRIDE + 2 * cx;
                #pragma unroll
                for (int i = 0; i < 8; ++i) {
                    float2 v2 = *(const float2*)(vrow + 32 * i);
                    o0[2*i]   += p0 * v2.x; o0[2*i+1] += p0 * v2.y;
                    o1[2*i]   += p1 * v2.x; o1[2*i+1] += p1 * v2.y;
                }
            }
        }
    }

    // finalize: divide by l, stage to SMEM for coalesced global store
    __syncthreads();
    {
        float inv0 = 1.f / l_s[ry];
        float inv1 = 1.f / l_s[ry + 32];
        #pragma unroll
        for (int i = 0; i < 8; ++i) {
            *(float2*)(vs + ry * VS_STRIDE + 2 * cx + 32 * i) =
                make_float2(o0[2*i] * inv0, o0[2*i+1] * inv0);
            *(float2*)(vs + (ry + 32) * VS_STRIDE + 2 * cx + 32 * i) =
                make_float2(o1[2*i] * inv1, o1[2*i+1] * inv1);
        }
    }
    __syncthreads();
    {
        const float* xb = x   + (size_t)b * CC * NN;
        float*       ob = out + (size_t)b * CC * NN;
        #pragma unroll
        for (int it = 0; it < 32; ++it) {
            int idx = tid + it * FTHREADS;   // 0..16383
            int c = idx >> 6, j = idx & 63;
            size_t gi = (size_t)c * NN + m0 + j;
            ob[gi] = xb[gi] + vs[j * VS_STRIDE + c];   // TEMPERATURE == 1.0
        }
    }
}

// ======================== launch ========================
extern "C" void kernel_launch(void* const* d_in, const int* in_sizes, int n_in,
                              void* d_out, int out_size)
{
    const float* x  = (const float*)d_in[0];
    const float* Wq = (const float*)d_in[1];
    const float* bq = (const float*)d_in[2];
    const float* Wk = (const float*)d_in[3];
    const float* bk = (const float*)d_in[4];
    const float* Wv = (const float*)d_in[5];
    const float* bv = (const float*)d_in[6];
    float* out = (float*)d_out;

    const size_t proj_smem = (size_t)(CC * XS_STRIDE + 8 * WS_STRIDE) * sizeof(float); // 143616
    const size_t attn_smem = (size_t)(BM * QS_STRIDE + CQK * KS_STRIDE + BM * SS_STRIDE +
                                      BN * VS_STRIDE + 3 * BM) * sizeof(float);        // 103168

    cudaFuncSetAttribute(proj_kernel, cudaFuncAttributeMaxDynamicSharedMemorySize, (int)proj_smem);
    cudaFuncSetAttribute(attn_kernel, cudaFuncAttributeMaxDynamicSharedMemorySize, (int)attn_smem);

    proj_kernel<<<dim3(NN / PTOK, BQ), PTHREADS, proj_smem>>>(x, Wq, bq, Wk, bk, Wv, bv);
    attn_kernel<<<dim3(NN / BM, BQ), FTHREADS, attn_smem>>>(x, out);
}

// round 2
// speedup vs baseline: 6.1951x; 6.1951x over previous
#include <cuda_runtime.h>
#include <cuda_bf16.h>
#include <cstdint>

// Problem constants
#define BQ  4
#define CC  256
#define CQK 32
#define NT  4096

// Scratch: q [B,N,32] bf16 (token-major), k [B,N,32] bf16 (token-major = K^T),
// v [B,256,N] bf16 (channel-major, native for PV B-fragments)
__device__ __nv_bfloat16 g_q[BQ * NT * CQK];
__device__ __nv_bfloat16 g_k[BQ * NT * CQK];
__device__ __nv_bfloat16 g_v[BQ * CC * NT];

// ---------------- PTX helpers ----------------
__device__ __forceinline__ uint32_t smem_u32(const void* p) {
    return (uint32_t)__cvta_generic_to_shared(p);
}
__device__ __forceinline__ void ldsm4(uint32_t& r0, uint32_t& r1, uint32_t& r2, uint32_t& r3,
                                      uint32_t addr) {
    asm volatile("ldmatrix.sync.aligned.m8n8.x4.shared.b16 {%0,%1,%2,%3}, [%4];"
                 : "=r"(r0), "=r"(r1), "=r"(r2), "=r"(r3) : "r"(addr));
}
__device__ __forceinline__ void mma16816(float* d, const uint32_t* a, uint32_t b0, uint32_t b1) {
    asm volatile("mma.sync.aligned.m16n8k16.row.col.f32.bf16.bf16.f32 "
                 "{%0,%1,%2,%3}, {%4,%5,%6,%7}, {%8,%9}, {%0,%1,%2,%3};"
                 : "+f"(d[0]), "+f"(d[1]), "+f"(d[2]), "+f"(d[3])
                 : "r"(a[0]), "r"(a[1]), "r"(a[2]), "r"(a[3]), "r"(b0), "r"(b1));
}
__device__ __forceinline__ uint32_t packbf(float lo, float hi) {
    uint32_t r;
    asm("cvt.rn.bf16x2.f32 %0, %1, %2;" : "=r"(r) : "f"(hi), "f"(lo));
    return r;
}

// ======================== projection kernel ========================
#define PTOK      128
#define PTHREADS  256
#define XS_STRIDE 132
#define WS_STRIDE 264

__global__ __launch_bounds__(PTHREADS)
void proj_kernel(const float* __restrict__ x,
                 const float* __restrict__ Wq, const float* __restrict__ bq,
                 const float* __restrict__ Wk, const float* __restrict__ bk,
                 const float* __restrict__ Wv, const float* __restrict__ bv)
{
    extern __shared__ float sm[];
    float* xs = sm;
    float* ws = sm + CC * XS_STRIDE;

    const int b    = blockIdx.y;
    const int n0   = blockIdx.x * PTOK;
    const int tid  = threadIdx.x;
    const int warp = tid >> 5;
    const int lane = tid & 31;

    const float* xb = x + (size_t)b * CC * NT;
    #pragma unroll
    for (int it = 0; it < (CC * PTOK / 4) / PTHREADS; ++it) {
        int idx = tid + it * PTHREADS;
        int c = idx >> 5, j4 = idx & 31;
        float4 v = *(const float4*)(xb + (size_t)c * NT + n0 + 4 * j4);
        *(float4*)(xs + c * XS_STRIDE + 4 * j4) = v;
    }
    __syncthreads();

    for (int oi = warp; oi < 320; oi += 8) {
        const float* wrow;
        float bias;
        if (oi < 32)      { wrow = Wq + oi * CC;        bias = bq[oi]; }
        else if (oi < 64) { wrow = Wk + (oi - 32) * CC; bias = bk[oi - 32]; }
        else              { wrow = Wv + (oi - 64) * CC; bias = bv[oi - 64]; }

        float* wbuf = ws + warp * WS_STRIDE;
        #pragma unroll
        for (int k8 = 0; k8 < 8; ++k8) wbuf[lane + 32 * k8] = wrow[lane + 32 * k8];
        __syncwarp();

        float a0 = 0.f, a1 = 0.f, a2 = 0.f, a3 = 0.f;
        const float* xp = xs + 4 * lane;
        #pragma unroll 8
        for (int c = 0; c < CC; ++c) {
            float  wv = wbuf[c];
            float4 xv = *(const float4*)(xp + c * XS_STRIDE);
            a0 += wv * xv.x; a1 += wv * xv.y; a2 += wv * xv.z; a3 += wv * xv.w;
        }
        a0 += bias; a1 += bias; a2 += bias; a3 += bias;

        const int t0 = n0 + 4 * lane;
        if (oi < 32) {
            __nv_bfloat16* qp = g_q + ((size_t)b * NT + t0) * CQK + oi;
            qp[0]        = __float2bfloat16(a0);
            qp[CQK]      = __float2bfloat16(a1);
            qp[2 * CQK]  = __float2bfloat16(a2);
            qp[3 * CQK]  = __float2bfloat16(a3);
        } else if (oi < 64) {
            __nv_bfloat16* kp = g_k + ((size_t)b * NT + t0) * CQK + (oi - 32);
            kp[0]        = __float2bfloat16(a0);
            kp[CQK]      = __float2bfloat16(a1);
            kp[2 * CQK]  = __float2bfloat16(a2);
            kp[3 * CQK]  = __float2bfloat16(a3);
        } else {
            __nv_bfloat162* vp = (__nv_bfloat162*)(g_v + ((size_t)b * CC + (oi - 64)) * NT + t0);
            vp[0] = __floats2bfloat162_rn(a0, a1);
            vp[1] = __floats2bfloat162_rn(a2, a3);
        }
        __syncwarp();
    }
}

// ======================== tensor-core flash attention ========================
// 256 threads = 8 warps. warpM = warp>>1 owns 16 query rows; warpN = warp&1 owns 128 V-channels.
#define BM 64
#define BN 64
#define QS_STRIDE 40   // bf16 elems; 80B rows, 16B aligned, conflict-free ldmatrix
#define KS_STRIDE 40
#define VS_STRIDE 72   // 144B rows
#define OS_STRIDE 264  // epilogue bf16 staging

__global__ __launch_bounds__(256)
void attn_kernel(const float* __restrict__ x, float* __restrict__ out)
{
    extern __shared__ __nv_bfloat16 smb[];
    __nv_bfloat16* qs = smb;                       // [64][40]
    __nv_bfloat16* ks = qs + BM * QS_STRIDE;       // [64][40]
    __nv_bfloat16* vs = ks + BN * KS_STRIDE;       // [256][72]

    const int b    = blockIdx.y;
    const int m0   = blockIdx.x * BM;
    const int tid  = threadIdx.x;
    const int warp = tid >> 5;
    const int lane = tid & 31;
    const int rm   = (warp >> 1) * 16;   // query-row base of this warp
    const int cn   = (warp & 1) * 128;   // V-channel base of this warp

    // ---- load Q tile [64][32] ----
    {
        int r = tid >> 2, c8 = tid & 3;
        *(uint4*)&qs[r * QS_STRIDE + 8 * c8] =
            *(const uint4*)&g_q[((size_t)b * NT + m0 + r) * CQK + 8 * c8];
    }
    __syncthreads();

    // ---- Q A-fragments (2 k-steps of 16) ----
    uint32_t aq[2][4];
    {
        uint32_t a0 = smem_u32(&qs[(rm + (lane & 15)) * QS_STRIDE + 8 * (lane >> 4)]);
        ldsm4(aq[0][0], aq[0][1], aq[0][2], aq[0][3], a0);
        uint32_t a1 = smem_u32(&qs[(rm + (lane & 15)) * QS_STRIDE + 16 + 8 * (lane >> 4)]);
        ldsm4(aq[1][0], aq[1][1], aq[1][2], aq[1][3], a1);
    }

    // softmax running state (rows rm+lane/4 and rm+lane/4+8; replicated across 4-lane group)
    float mr0 = -1e30f, mr1 = -1e30f, lr0 = 0.f, lr1 = 0.f;

    float o[16][4];
    #pragma unroll
    for (int j = 0; j < 16; ++j) { o[j][0] = 0.f; o[j][1] = 0.f; o[j][2] = 0.f; o[j][3] = 0.f; }

    const __nv_bfloat16* kb = g_k + (size_t)b * NT * CQK;
    const __nv_bfloat16* vb = g_v + (size_t)b * CC * NT;

    // precomputed ldmatrix lane offsets
    const int ks_row_off = (lane & 7) + 8 * ((lane >> 4) & 1);
    const int ks_col_off = 8 * ((lane >> 3) & 1);

    for (int nt = 0; nt < NT; nt += BN) {
        __syncthreads();
        // ---- load K tile [64][32] bf16 ----
        {
            int r = tid >> 2, c8 = tid & 3;
            *(uint4*)&ks[r * KS_STRIDE + 8 * c8] =
                *(const uint4*)&kb[(size_t)(nt + r) * CQK + 8 * c8];
        }
        // ---- load V tile [256 c][64 n] bf16 (native layout, no transpose) ----
        #pragma unroll
        for (int it = 0; it < 8; ++it) {
            int idx = tid + it * 256;
            int c = idx >> 3, j = idx & 7;
            *(uint4*)&vs[c * VS_STRIDE + 8 * j] =
                *(const uint4*)&vb[(size_t)c * NT + nt + 8 * j];
        }
        __syncthreads();

        // ---- S = Q · K^T : 8 n-tiles of 8 cols ----
        float s[8][4];
        #pragma unroll
        for (int j = 0; j < 8; ++j) { s[j][0]=0.f; s[j][1]=0.f; s[j][2]=0.f; s[j][3]=0.f; }
        #pragma unroll
        for (int jj = 0; jj < 4; ++jj) {
            #pragma unroll
            for (int kk = 0; kk < 2; ++kk) {
                uint32_t b0, b1, b2, b3;
                uint32_t addr = smem_u32(&ks[(16 * jj + ks_row_off) * KS_STRIDE +
                                             16 * kk + ks_col_off]);
                ldsm4(b0, b1, b2, b3, addr);
                mma16816(s[2 * jj],     aq[kk], b0, b1);
                mma16816(s[2 * jj + 1], aq[kk], b2, b3);
            }
        }

        // ---- online softmax ----
        float mx0 = -1e30f, mx1 = -1e30f;
        #pragma unroll
        for (int j = 0; j < 8; ++j) {
            mx0 = fmaxf(mx0, fmaxf(s[j][0], s[j][1]));
            mx1 = fmaxf(mx1, fmaxf(s[j][2], s[j][3]));
        }
        mx0 = fmaxf(mx0, __shfl_xor_sync(0xffffffffu, mx0, 1));
        mx0 = fmaxf(mx0, __shfl_xor_sync(0xffffffffu, mx0, 2));
        mx1 = fmaxf(mx1, __shfl_xor_sync(0xffffffffu, mx1, 1));
        mx1 = fmaxf(mx1, __shfl_xor_sync(0xffffffffu, mx1, 2));

        float mn0 = fmaxf(mr0, mx0), mn1 = fmaxf(mr1, mx1);
        float sc0 = __expf(mr0 - mn0), sc1 = __expf(mr1 - mn1);
        mr0 = mn0; mr1 = mn1;

        float ts0 = 0.f, ts1 = 0.f;
        #pragma unroll
        for (int j = 0; j < 8; ++j) {
            s[j][0] = __expf(s[j][0] - mn0);
            s[j][1] = __expf(s[j][1] - mn0);
            s[j][2] = __expf(s[j][2] - mn1);
            s[j][3] = __expf(s[j][3] - mn1);
            ts0 += s[j][0] + s[j][1];
            ts1 += s[j][2] + s[j][3];
        }
        ts0 += __shfl_xor_sync(0xffffffffu, ts0, 1);
        ts0 += __shfl_xor_sync(0xffffffffu, ts0, 2);
        ts1 += __shfl_xor_sync(0xffffffffu, ts1, 1);
        ts1 += __shfl_xor_sync(0xffffffffu, ts1, 2);
        lr0 = lr0 * sc0 + ts0;
        lr1 = lr1 * sc1 + ts1;

        // ---- rescale O ----
        #pragma unroll
        for (int j = 0; j < 16; ++j) {
            o[j][0] *= sc0; o[j][1] *= sc0; o[j][2] *= sc1; o[j][3] *= sc1;
        }

        // ---- pack P to bf16 A-fragments (4 k-steps of 16 kv-tokens) ----
        uint32_t pa[4][4];
        #pragma unroll
        for (int kk = 0; kk < 4; ++kk) {
            pa[kk][0] = packbf(s[2 * kk][0],     s[2 * kk][1]);
            pa[kk][1] = packbf(s[2 * kk][2],     s[2 * kk][3]);
            pa[kk][2] = packbf(s[2 * kk + 1][0], s[2 * kk + 1][1]);
            pa[kk][3] = packbf(s[2 * kk + 1][2], s[2 * kk + 1][3]);
        }

        // ---- O += P · V  (V B-frags: rows = channel, cols = kv-token) ----
        #pragma unroll
        for (int kk = 0; kk < 4; ++kk) {
            #pragma unroll
            for (int ct = 0; ct < 8; ++ct) {
                uint32_t b0, b1, b2, b3;
                uint32_t addr = smem_u32(&vs[(cn + 16 * ct + ks_row_off) * VS_STRIDE +
                                             16 * kk + ks_col_off]);
                ldsm4(b0, b1, b2, b3, addr);
                mma16816(o[2 * ct],     pa[kk], b0, b1);
                mma16816(o[2 * ct + 1], pa[kk], b2, b3);
            }
        }
    }

    // ---- finalize: O /= l, stage bf16 to SMEM, fused residual store ----
    __syncthreads();
    __nv_bfloat16* os = smb;   // [64][264] bf16, overlays qs/ks/vs
    {
        float il0 = 1.f / lr0, il1 = 1.f / lr1;
        int r0 = rm + (lane >> 2);
        #pragma unroll
        for (int j = 0; j < 16; ++j) {
            int col = cn + 8 * j + 2 * (lane & 3);
            *(__nv_bfloat162*)&os[r0 * OS_STRIDE + col] =
                __floats2bfloat162_rn(o[j][0] * il0, o[j][1] * il0);
            *(__nv_bfloat162*)&os[(r0 + 8) * OS_STRIDE + col] =
                __floats2bfloat162_rn(o[j][2] * il1, o[j][3] * il1);
        }
    }
    __syncthreads();
    {
        const float* xb = x   + (size_t)b * CC * NT;
        float*       ob = out + (size_t)b * CC * NT;
        #pragma unroll
        for (int it = 0; it < 64; ++it) {
            int idx = tid + it * 256;
            int c = idx >> 6, j = idx & 63;
            size_t gi = (size_t)c * NT + m0 + j;
            ob[gi] = xb[gi] + __bfloat162float(os[j * OS_STRIDE + c]);
        }
    }
}

// ======================== launch ========================
extern "C" void kernel_launch(void* const* d_in, const int* in_sizes, int n_in,
                              void* d_out, int out_size)
{
    const float* x  = (const float*)d_in[0];
    const float* Wq = (const float*)d_in[1];
    const float* bq = (const float*)d_in[2];
    const float* Wk = (const float*)d_in[3];
    const float* bk = (const float*)d_in[4];
    const float* Wv = (const float*)d_in[5];
    const float* bv = (const float*)d_in[6];
    float* out = (float*)d_out;

    const size_t proj_smem = (size_t)(CC * XS_STRIDE + 8 * WS_STRIDE) * sizeof(float);
    const size_t attn_smem = (size_t)(BM * QS_STRIDE + BN * KS_STRIDE + CC * VS_STRIDE)
                             * sizeof(__nv_bfloat16);   // 47104 B

    cudaFuncSetAttribute(proj_kernel, cudaFuncAttributeMaxDynamicSharedMemorySize, (int)proj_smem);
    cudaFuncSetAttribute(attn_kernel, cudaFuncAttributeMaxDynamicSharedMemorySize, (int)attn_smem);

    proj_kernel<<<dim3(NT / PTOK, BQ), PTHREADS, proj_smem>>>(x, Wq, bq, Wk, bk, Wv, bv);
    attn_kernel<<<dim3(NT / BM, BQ), 256, attn_smem>>>(x, out);
}

// round 3
// speedup vs baseline: 13.9701x; 2.2550x over previous
#include <cuda_runtime.h>
#include <cuda_bf16.h>
#include <cstdint>

#define BQ  4
#define CC  256
#define CQK 32
#define NT  4096
#define LOG2E 1.4426950408889634f

// Scratch: q/k token-major [B,N,32] bf16, v channel-major [B,256,N] bf16,
// W packed bf16 [320][256] (q rows pre-scaled by log2e)
__device__ __align__(16) __nv_bfloat16 g_q[BQ * NT * CQK];
__device__ __align__(16) __nv_bfloat16 g_k[BQ * NT * CQK];
__device__ __align__(16) __nv_bfloat16 g_v[BQ * CC * NT];
__device__ __align__(16) __nv_bfloat16 g_wb[320 * CC];

// ---------------- PTX helpers ----------------
__device__ __forceinline__ uint32_t smem_u32(const void* p) {
    return (uint32_t)__cvta_generic_to_shared(p);
}
__device__ __forceinline__ void ldsm4(uint32_t& r0, uint32_t& r1, uint32_t& r2, uint32_t& r3,
                                      uint32_t addr) {
    asm volatile("ldmatrix.sync.aligned.m8n8.x4.shared.b16 {%0,%1,%2,%3}, [%4];"
                 : "=r"(r0), "=r"(r1), "=r"(r2), "=r"(r3) : "r"(addr));
}
__device__ __forceinline__ void ldsm4t(uint32_t& r0, uint32_t& r1, uint32_t& r2, uint32_t& r3,
                                       uint32_t addr) {
    asm volatile("ldmatrix.sync.aligned.m8n8.x4.trans.shared.b16 {%0,%1,%2,%3}, [%4];"
                 : "=r"(r0), "=r"(r1), "=r"(r2), "=r"(r3) : "r"(addr));
}
__device__ __forceinline__ void mma16816(float* d, const uint32_t* a, uint32_t b0, uint32_t b1) {
    asm volatile("mma.sync.aligned.m16n8k16.row.col.f32.bf16.bf16.f32 "
                 "{%0,%1,%2,%3}, {%4,%5,%6,%7}, {%8,%9}, {%0,%1,%2,%3};"
                 : "+f"(d[0]), "+f"(d[1]), "+f"(d[2]), "+f"(d[3])
                 : "r"(a[0]), "r"(a[1]), "r"(a[2]), "r"(a[3]), "r"(b0), "r"(b1));
}
__device__ __forceinline__ uint32_t packbf(float lo, float hi) {
    uint32_t r;
    asm("cvt.rn.bf16x2.f32 %0, %1, %2;" : "=r"(r) : "f"(hi), "f"(lo));
    return r;
}
__device__ __forceinline__ float ex2(float x) {
    float y;
    asm("ex2.approx.f32 %0, %1;" : "=f"(y) : "f"(x));
    return y;
}
__device__ __forceinline__ void cp16(uint32_t s, const void* g) {
    asm volatile("cp.async.cg.shared.global [%0], [%1], 16;" :: "r"(s), "l"(g));
}
#define CP_COMMIT() asm volatile("cp.async.commit_group;")
#define CP_WAIT(n)  asm volatile("cp.async.wait_group %0;" :: "n"(n))

// ======================== W convert kernel ========================
__global__ void wconv_kernel(const float* __restrict__ Wq, const float* __restrict__ Wk,
                             const float* __restrict__ Wv)
{
    int f = blockIdx.x * 256 + threadIdx.x;   // float4 index over [320][64]
    if (f >= 320 * 64) return;
    int row = f >> 6, c4 = f & 63;
    const float* src; float scl = 1.f;
    if (row < 32)      { src = Wq + row * CC;        scl = LOG2E; }
    else if (row < 64) { src = Wk + (row - 32) * CC; }
    else               { src = Wv + (row - 64) * CC; }
    float4 v = *(const float4*)(src + 4 * c4);
    uint32_t lo = packbf(v.x * scl, v.y * scl);
    uint32_t hi = packbf(v.z * scl, v.w * scl);
    *(uint2*)&g_wb[row * CC + 4 * c4] = make_uint2(lo, hi);
}

// ======================== projection: bf16 HMMA GEMM ========================
// C[64 tok][320 out] = x^T[tok][c] * W^T[c][out]. grid (64,4). 8 warps = 4m x 2n.
#define TN 64
#define XS 72    // xs stride (bf16)
#define WSS 40   // ws stride (bf16)

__global__ __launch_bounds__(256, 2)
void proj_kernel(const float* __restrict__ x,
                 const float* __restrict__ bq, const float* __restrict__ bk,
                 const float* __restrict__ bv)
{
    extern __shared__ __nv_bfloat16 smp[];
    __nv_bfloat16* xs = smp;              // [256][72]
    __nv_bfloat16* ws = smp + CC * XS;    // [2][320][40]

    const int b    = blockIdx.y;
    const int tok0 = blockIdx.x * TN;
    const int tid  = threadIdx.x;
    const int lane = tid & 31;
    const int m0   = ((tid >> 5) >> 1) * 16;   // 16 tokens
    const int n0   = ((tid >> 5) & 1) * 160;   // 160 outputs

    auto load_w = [&](int buf, int kc) {
        #pragma unroll
        for (int it = 0; it < 5; ++it) {
            int idx = tid + it * 256;          // 0..1279
            int r = idx >> 2, q = idx & 3;
            cp16(smem_u32(&ws[buf * 320 * WSS + r * WSS + 8 * q]),
                 &g_wb[r * CC + kc * 32 + 8 * q]);
        }
    };
    load_w(0, 0); CP_COMMIT();

    // x tile [256 c][64 tok] fp32 -> bf16 smem
    const float* xb = x + (size_t)b * CC * NT;
    #pragma unroll
    for (int it = 0; it < 16; ++it) {
        int idx = tid + it * 256;
        int c = idx >> 4, j4 = idx & 15;
        float4 v = *(const float4*)(xb + (size_t)c * NT + tok0 + 4 * j4);
        *(uint2*)&xs[c * XS + 4 * j4] = make_uint2(packbf(v.x, v.y), packbf(v.z, v.w));
    }

    float acc[20][4];
    #pragma unroll
    for (int j = 0; j < 20; ++j) { acc[j][0]=0.f; acc[j][1]=0.f; acc[j][2]=0.f; acc[j][3]=0.f; }

    const int a_row = 8 * (lane >> 4) + (lane & 7);        // + k
    const int a_col = m0 + 8 * ((lane >> 3) & 1);
    const int b_row = (lane & 7) + 8 * ((lane >> 4) & 1);  // + n
    const int b_col = 8 * ((lane >> 3) & 1);               // + k local

    for (int kc = 0; kc < 8; ++kc) {
        int buf = kc & 1;
        if (kc < 7) { load_w(buf ^ 1, kc + 1); CP_COMMIT(); CP_WAIT(1); }
        else        { CP_WAIT(0); }
        __syncthreads();
        const __nv_bfloat16* wb = ws + buf * 320 * WSS;
        #pragma unroll
        for (int st = 0; st < 2; ++st) {
            uint32_t a[4];
            ldsm4t(a[0], a[1], a[2], a[3],
                   smem_u32(&xs[(kc * 32 + st * 16 + a_row) * XS + a_col]));
            #pragma unroll
            for (int t = 0; t < 10; ++t) {
                uint32_t b0, b1, b2, b3;
                ldsm4(b0, b1, b2, b3,
                      smem_u32(&wb[(n0 + 16 * t + b_row) * WSS + st * 16 + b_col]));
                mma16816(acc[2 * t],     a, b0, b1);
                mma16816(acc[2 * t + 1], a, b2, b3);
            }
        }
        __syncthreads();
    }

    // epilogue: bias + bf16, stage os[320 out][72 tok]
    __nv_bfloat16* os = smp;
    {
        int r0 = m0 + (lane >> 2);
        #pragma unroll
        for (int j = 0; j < 20; ++j) {
            int n = n0 + 8 * j + 2 * (lane & 3);
            float b0f, b1f;
            if (n < 32)      { b0f = bq[n] * LOG2E; b1f = bq[n + 1] * LOG2E; }
            else if (n < 64) { b0f = bk[n - 32];    b1f = bk[n - 31]; }
            else             { b0f = bv[n - 64];    b1f = bv[n - 63]; }
            os[n * XS + r0]           = __float2bfloat16(acc[j][0] + b0f);
            os[(n + 1) * XS + r0]     = __float2bfloat16(acc[j][1] + b1f);
            os[n * XS + r0 + 8]       = __float2bfloat16(acc[j][2] + b0f);
            os[(n + 1) * XS + r0 + 8] = __float2bfloat16(acc[j][3] + b1f);
        }
    }
    __syncthreads();

    // q,k: token-major 16B stores
    {
        int tok = tid >> 2, g = tid & 3;
        uint32_t pq[4], pk[4];
        #pragma unroll
        for (int i = 0; i < 4; ++i) {
            pq[i] = (uint32_t)__bfloat16_as_ushort(os[(8 * g + 2 * i) * XS + tok]) |
                    ((uint32_t)__bfloat16_as_ushort(os[(8 * g + 2 * i + 1) * XS + tok]) << 16);
            pk[i] = (uint32_t)__bfloat16_as_ushort(os[(32 + 8 * g + 2 * i) * XS + tok]) |
                    ((uint32_t)__bfloat16_as_ushort(os[(32 + 8 * g + 2 * i + 1) * XS + tok]) << 16);
        }
        *(uint4*)&g_q[((size_t)b * NT + tok0 + tok) * CQK + 8 * g] =
            make_uint4(pq[0], pq[1], pq[2], pq[3]);
        *(uint4*)&g_k[((size_t)b * NT + tok0 + tok) * CQK + 8 * g] =
            make_uint4(pk[0], pk[1], pk[2], pk[3]);
    }
    // v: channel-major rows, coalesced 16B
    #pragma unroll
    for (int it = 0; it < 8; ++it) {
        int idx = tid + it * 256;   // 0..2047
        int cv = idx >> 3, jj = idx & 7;
        uint4 val = *(uint4*)&os[(64 + cv) * XS + 8 * jj];
        *(uint4*)&g_v[((size_t)b * CC + cv) * NT + tok0 + 8 * jj] = val;
    }
}

// ======================== tensor-core flash attention ========================
#define BM 64
#define BN 64
#define QS_STRIDE 40
#define KS_STRIDE 40
#define VS_STRIDE 72
#define OS_STRIDE 264
#define KTILE (BN * KS_STRIDE)     // 2560
#define VTILE (CC * VS_STRIDE)     // 18432

__global__ __launch_bounds__(256, 2)
void attn_kernel(const float* __restrict__ x, float* __restrict__ out)
{
    extern __shared__ __nv_bfloat16 smb[];
    __nv_bfloat16* qs = smb;                        // [64][40]
    __nv_bfloat16* ks = qs + BM * QS_STRIDE;        // [2][64][40]
    __nv_bfloat16* vs = ks + 2 * KTILE;             // [2][256][72]

    const int b    = blockIdx.y;
    const int m0   = blockIdx.x * BM;
    const int tid  = threadIdx.x;
    const int warp = tid >> 5;
    const int lane = tid & 31;
    const int rm   = (warp >> 1) * 16;
    const int cn   = (warp & 1) * 128;

    const __nv_bfloat16* kb = g_k + (size_t)b * NT * CQK;
    const __nv_bfloat16* vb = g_v + (size_t)b * CC * NT;

    auto load_kv = [&](int buf, int nt) {
        {   // K tile [64][32]
            int r = tid >> 2, c8 = tid & 3;
            cp16(smem_u32(&ks[buf * KTILE + r * KS_STRIDE + 8 * c8]),
                 &kb[(size_t)(nt + r) * CQK + 8 * c8]);
        }
        #pragma unroll
        for (int it = 0; it < 8; ++it) {   // V tile [256][64]
            int idx = tid + it * 256;
            int c = idx >> 3, j = idx & 7;
            cp16(smem_u32(&vs[buf * VTILE + c * VS_STRIDE + 8 * j]),
                 &vb[(size_t)c * NT + nt + 8 * j]);
        }
    };

    load_kv(0, 0); CP_COMMIT();

    // Q tile + fragments
    {
        int r = tid >> 2, c8 = tid & 3;
        *(uint4*)&qs[r * QS_STRIDE + 8 * c8] =
            *(const uint4*)&g_q[((size_t)b * NT + m0 + r) * CQK + 8 * c8];
    }
    __syncthreads();
    uint32_t aq[2][4];
    ldsm4(aq[0][0], aq[0][1], aq[0][2], aq[0][3],
          smem_u32(&qs[(rm + (lane & 15)) * QS_STRIDE + 8 * (lane >> 4)]));
    ldsm4(aq[1][0], aq[1][1], aq[1][2], aq[1][3],
          smem_u32(&qs[(rm + (lane & 15)) * QS_STRIDE + 16 + 8 * (lane >> 4)]));

    float mr0 = -1e30f, mr1 = -1e30f, lr0 = 0.f, lr1 = 0.f;
    float o[16][4];
    #pragma unroll
    for (int j = 0; j < 16; ++j) { o[j][0]=0.f; o[j][1]=0.f; o[j][2]=0.f; o[j][3]=0.f; }

    const int ks_row_off = (lane & 7) + 8 * ((lane >> 4) & 1);
    const int ks_col_off = 8 * ((lane >> 3) & 1);

    for (int t = 0; t < NT / BN; ++t) {
        const int cur = t & 1;
        if (t + 1 < NT / BN) { load_kv(cur ^ 1, (t + 1) * BN); CP_COMMIT(); CP_WAIT(1); }
        else                 { CP_WAIT(0); }
        __syncthreads();
        const __nv_bfloat16* ksb = ks + cur * KTILE;
        const __nv_bfloat16* vsb = vs + cur * VTILE;

        // S = Q K^T (log2e pre-folded into q)
        float s[8][4];
        #pragma unroll
        for (int j = 0; j < 8; ++j) { s[j][0]=0.f; s[j][1]=0.f; s[j][2]=0.f; s[j][3]=0.f; }
        #pragma unroll
        for (int jj = 0; jj < 4; ++jj) {
            #pragma unroll
            for (int kk = 0; kk < 2; ++kk) {
                uint32_t b0, b1, b2, b3;
                ldsm4(b0, b1, b2, b3,
                      smem_u32(&ksb[(16 * jj + ks_row_off) * KS_STRIDE + 16 * kk + ks_col_off]));
                mma16816(s[2 * jj],     aq[kk], b0, b1);
                mma16816(s[2 * jj + 1], aq[kk], b2, b3);
            }
        }

        // online softmax (base-2 domain)
        float mx0 = -1e30f, mx1 = -1e30f;
        #pragma unroll
        for (int j = 0; j < 8; ++j) {
            mx0 = fmaxf(mx0, fmaxf(s[j][0], s[j][1]));
            mx1 = fmaxf(mx1, fmaxf(s[j][2], s[j][3]));
        }
        mx0 = fmaxf(mx0, __shfl_xor_sync(0xffffffffu, mx0, 1));
        mx0 = fmaxf(mx0, __shfl_xor_sync(0xffffffffu, mx0, 2));
        mx1 = fmaxf(mx1, __shfl_xor_sync(0xffffffffu, mx1, 1));
        mx1 = fmaxf(mx1, __shfl_xor_sync(0xffffffffu, mx1, 2));

        float mn0 = fmaxf(mr0, mx0), mn1 = fmaxf(mr1, mx1);
        bool nochange = (mn0 == mr0) & (mn1 == mr1);
        float sc0 = ex2(mr0 - mn0), sc1 = ex2(mr1 - mn1);
        mr0 = mn0; mr1 = mn1;

        float ts0 = 0.f, ts1 = 0.f;
        #pragma unroll
        for (int j = 0; j < 8; ++j) {
            s[j][0] = ex2(s[j][0] - mn0);
            s[j][1] = ex2(s[j][1] - mn0);
            s[j][2] = ex2(s[j][2] - mn1);
            s[j][3] = ex2(s[j][3] - mn1);
            ts0 += s[j][0] + s[j][1];
            ts1 += s[j][2] + s[j][3];
        }
        ts0 += __shfl_xor_sync(0xffffffffu, ts0, 1);
        ts0 += __shfl_xor_sync(0xffffffffu, ts0, 2);
        ts1 += __shfl_xor_sync(0xffffffffu, ts1, 1);
        ts1 += __shfl_xor_sync(0xffffffffu, ts1, 2);
        lr0 = lr0 * sc0 + ts0;
        lr1 = lr1 * sc1 + ts1;

        if (!__all_sync(0xffffffffu, nochange)) {
            #pragma unroll
            for (int j = 0; j < 16; ++j) {
                o[j][0] *= sc0; o[j][1] *= sc0; o[j][2] *= sc1; o[j][3] *= sc1;
            }
        }

        // pack P, O += P V
        uint32_t pa[4][4];
        #pragma unroll
        for (int kk = 0; kk < 4; ++kk) {
            pa[kk][0] = packbf(s[2 * kk][0],     s[2 * kk][1]);
            pa[kk][1] = packbf(s[2 * kk][2],     s[2 * kk][3]);
            pa[kk][2] = packbf(s[2 * kk + 1][0], s[2 * kk + 1][1]);
            pa[kk][3] = packbf(s[2 * kk + 1][2], s[2 * kk + 1][3]);
        }
        #pragma unroll
        for (int kk = 0; kk < 4; ++kk) {
            #pragma unroll
            for (int ct = 0; ct < 8; ++ct) {
                uint32_t b0, b1, b2, b3;
                ldsm4(b0, b1, b2, b3,
                      smem_u32(&vsb[(cn + 16 * ct + ks_row_off) * VS_STRIDE + 16 * kk + ks_col_off]));
                mma16816(o[2 * ct],     pa[kk], b0, b1);
                mma16816(o[2 * ct + 1], pa[kk], b2, b3);
            }
        }
        __syncthreads();
    }

    // finalize
    __nv_bfloat16* os = smb;
    {
        float il0 = 1.f / lr0, il1 = 1.f / lr1;
        int r0 = rm + (lane >> 2);
        #pragma unroll
        for (int j = 0; j < 16; ++j) {
            int col = cn + 8 * j + 2 * (lane & 3);
            *(__nv_bfloat162*)&os[r0 * OS_STRIDE + col] =
                __floats2bfloat162_rn(o[j][0] * il0, o[j][1] * il0);
            *(__nv_bfloat162*)&os[(r0 + 8) * OS_STRIDE + col] =
                __floats2bfloat162_rn(o[j][2] * il1, o[j][3] * il1);
        }
    }
    __syncthreads();
    {
        const float* xb = x   + (size_t)b * CC * NT;
        float*       ob = out + (size_t)b * CC * NT;
        #pragma unroll
        for (int it = 0; it < 64; ++it) {
            int idx = tid + it * 256;
            int c = idx >> 6, j = idx & 63;
            size_t gi = (size_t)c * NT + m0 + j;
            ob[gi] = xb[gi] + __bfloat162float(os[j * OS_STRIDE + c]);
        }
    }
}

// ======================== launch ========================
extern "C" void kernel_launch(void* const* d_in, const int* in_sizes, int n_in,
                              void* d_out, int out_size)
{
    const float* x  = (const float*)d_in[0];
    const float* Wq = (const float*)d_in[1];
    const float* bq = (const float*)d_in[2];
    const float* Wk = (const float*)d_in[3];
    const float* bk = (const float*)d_in[4];
    const float* Wv = (const float*)d_in[5];
    const float* bv = (const float*)d_in[6];
    float* out = (float*)d_out;

    const size_t proj_smem = (size_t)(CC * XS + 2 * 320 * WSS) * sizeof(__nv_bfloat16); // 88064
    const size_t attn_smem = (size_t)(BM * QS_STRIDE + 2 * KTILE + 2 * VTILE)
                             * sizeof(__nv_bfloat16);                                    // 89088

    cudaFuncSetAttribute(proj_kernel, cudaFuncAttributeMaxDynamicSharedMemorySize, (int)proj_smem);
    cudaFuncSetAttribute(attn_kernel, cudaFuncAttributeMaxDynamicSharedMemorySize, (int)attn_smem);

    wconv_kernel<<<80, 256>>>(Wq, Wk, Wv);
    proj_kernel<<<dim3(NT / TN, BQ), 256, proj_smem>>>(x, bq, bk, bv);
    attn_kernel<<<dim3(NT / BM, BQ), 256, attn_smem>>>(x, out);
}